// round 1
// baseline (speedup 1.0000x reference)
#include <cuda_runtime.h>
#include <cuda_bf16.h>

#define NMAX 100000
#define EMAX 800000

// ---------------- scratch (device globals; no runtime allocation) ------------
__device__ float4 g_h2  [NMAX * 6];    // [N,24] padded (23 + 1 zero)
__device__ float4 g_q1  [NMAX * 48];   // [N,192]
__device__ float4 g_k1  [NMAX * 48];
__device__ float4 g_v1  [NMAX * 48];
__device__ float4 g_acc1[NMAX * 48];   // skip + aggregated messages (conv1 out, pre-elu)
__device__ float  g_ex1 [EMAX * 8];
__device__ float  g_den1[NMAX * 8];
__device__ float4 g_q2  [NMAX * 16];   // [N,64]
__device__ float4 g_k2  [NMAX * 16];
__device__ float4 g_v2  [NMAX * 16];
__device__ float4 g_acc2[NMAX * 16];   // conv2 out, pre-elu
__device__ float  g_ex2 [EMAX * 8];
__device__ float  g_den2[NMAX * 8];

__device__ __forceinline__ float eluf(float x) { return x > 0.f ? x : expm1f(x); }

// ---------------- zero the softmax denominators ------------------------------
__global__ void k_zero(int n8) {
    int i = blockIdx.x * blockDim.x + threadIdx.x;
    if (i < n8) { g_den1[i] = 0.f; g_den2[i] = 0.f; }
}

// ---------------- h2 = elu(elu(x@A+bA)@B+bB), padded to 24 -------------------
__global__ void k_h2(const float* __restrict__ x,
                     const float* __restrict__ Aw, const float* __restrict__ Ab,
                     const float* __restrict__ Bw, const float* __restrict__ Bb,
                     int n) {
    __shared__ float sA[23 * 23], sB[23 * 23], sbA[23], sbB[23];
    __shared__ float sx[256 * 23];
    int tid = threadIdx.x;
    for (int i = tid; i < 23 * 23; i += 256) { sA[i] = Aw[i]; sB[i] = Bw[i]; }
    if (tid < 23) { sbA[tid] = Ab[tid]; sbB[tid] = Bb[tid]; }
    int base = blockIdx.x * 256;
    int cnt  = min(256, n - base);
    for (int i = tid; i < cnt * 23; i += 256) sx[i] = x[base * 23 + i];
    __syncthreads();
    if (tid < cnt) {
        const float* xr = &sx[tid * 23];
        float h1[23];
        #pragma unroll
        for (int j = 0; j < 23; j++) {
            float a = sbA[j];
            #pragma unroll
            for (int k = 0; k < 23; k++) a += xr[k] * sA[k * 23 + j];
            h1[j] = eluf(a);
        }
        float* out = (float*)g_h2 + (base + tid) * 24;
        #pragma unroll
        for (int j = 0; j < 23; j++) {
            float a = sbB[j];
            #pragma unroll
            for (int k = 0; k < 23; k++) a += h1[k] * sB[k * 23 + j];
            out[j] = eluf(a);
        }
        out[23] = 0.f;
    }
}

// ---------------- conv1 node GEMM: [N,24]@[24,768] -> q1,k1,v1,acc1(skip) ----
__global__ void k_gemm1(const float* __restrict__ qw, const float* __restrict__ qb,
                        const float* __restrict__ kw, const float* __restrict__ kb,
                        const float* __restrict__ vw, const float* __restrict__ vb,
                        const float* __restrict__ sw, const float* __restrict__ sb,
                        int n) {
    __shared__ float4 sh[128 * 6];
    int tid = threadIdx.x;                  // 768 threads
    int arr = tid / 192, cc = tid % 192;
    const float* W = arr == 0 ? qw : arr == 1 ? kw : arr == 2 ? vw : sw;
    const float* B = arr == 0 ? qb : arr == 1 ? kb : arr == 2 ? vb : sb;
    float* outp = (float*)(arr == 0 ? g_q1 : arr == 1 ? g_k1 : arr == 2 ? g_v1 : g_acc1);
    float w[24];
    #pragma unroll
    for (int k = 0; k < 23; k++) w[k] = W[k * 192 + cc];
    w[23] = 0.f;
    float bias = B[cc];
    int base = blockIdx.x * 128;
    int cnt  = min(128, n - base);
    for (int i = tid; i < cnt * 6; i += 768) sh[i] = g_h2[base * 6 + i];
    __syncthreads();
    for (int nn = 0; nn < cnt; nn++) {
        float a = bias;
        #pragma unroll
        for (int k4 = 0; k4 < 6; k4++) {
            float4 h = sh[nn * 6 + k4];
            a += h.x * w[4 * k4] + h.y * w[4 * k4 + 1] + h.z * w[4 * k4 + 2] + h.w * w[4 * k4 + 3];
        }
        outp[(base + nn) * 192 + cc] = a;
    }
}

// ---------------- conv1 edge pass 1: ex=exp(logit), denom accumulate ---------
__global__ void k_edge1(const int* __restrict__ src, const int* __restrict__ dst,
                        const float* __restrict__ ea, const float* __restrict__ ew, int E) {
    __shared__ float sW[1344];              // e1_w [7,192]
    int tid = threadIdx.x;
    for (int i = tid; i < 1344; i += 256) sW[i] = ew[i];
    __syncthreads();
    int e = (blockIdx.x * 256 + tid) >> 5;
    int lane = tid & 31;
    if (e >= E) return;
    int s = src[e], d = dst[e];
    float eav[7];
    #pragma unroll
    for (int t = 0; t < 7; t++) eav[t] = ea[e * 7 + t];
    const float* qr = (const float*)g_q1 + d * 192 + lane * 6;
    const float* kr = (const float*)g_k1 + s * 192 + lane * 6;
    float qv[6], kv[6];
    { float2 a = *(const float2*)(qr);     qv[0]=a.x; qv[1]=a.y;
      float2 b = *(const float2*)(qr + 2); qv[2]=b.x; qv[3]=b.y;
      float2 c = *(const float2*)(qr + 4); qv[4]=c.x; qv[5]=c.y;
      float2 p = *(const float2*)(kr);     kv[0]=p.x; kv[1]=p.y;
      float2 q = *(const float2*)(kr + 2); kv[2]=q.x; kv[3]=q.y;
      float2 r = *(const float2*)(kr + 4); kv[4]=r.x; kv[5]=r.y; }
    const float* wj = &sW[lane * 6];
    float part = 0.f;
    #pragma unroll
    for (int j = 0; j < 6; j++) {
        float ev = 0.f;
        #pragma unroll
        for (int t = 0; t < 7; t++) ev += eav[t] * wj[t * 192 + j];
        part += qv[j] * (kv[j] + ev);
    }
    part += __shfl_xor_sync(0xffffffffu, part, 1);
    part += __shfl_xor_sync(0xffffffffu, part, 2);
    if ((lane & 3) == 0) {
        int h = lane >> 2;
        float ex = __expf(part * 0.20412414523193154f);   // 1/sqrt(24)
        g_ex1[e * 8 + h] = ex;
        atomicAdd(&g_den1[d * 8 + h], ex);
    }
}

// ---------------- conv1 edge pass 2: scatter alpha*(v+e) ---------------------
__global__ void k_edge2(const int* __restrict__ src, const int* __restrict__ dst,
                        const float* __restrict__ ea, const float* __restrict__ ew, int E) {
    __shared__ float sW[1344];
    int tid = threadIdx.x;
    for (int i = tid; i < 1344; i += 256) sW[i] = ew[i];
    __syncthreads();
    int e = (blockIdx.x * 256 + tid) >> 5;
    int lane = tid & 31;
    if (e >= E) return;
    int s = src[e], d = dst[e];
    float eav[7];
    #pragma unroll
    for (int t = 0; t < 7; t++) eav[t] = ea[e * 7 + t];
    float a = 0.f;
    if (lane < 8) a = g_ex1[e * 8 + lane] / g_den1[d * 8 + lane];
    float al1 = __shfl_sync(0xffffffffu, a, lane / 6);          // head of chunk "lane"
    float al2 = __shfl_sync(0xffffffffu, a, (lane + 32) / 6);   // head of chunk "lane+32"
    const float4* vr = g_v1 + s * 48;
    float4* ar = g_acc1 + d * 48;
    {
        int c = lane;
        float4 v = vr[c];
        const float* wc = &sW[4 * c];
        float ex0=0.f, ex1=0.f, ex2=0.f, ex3=0.f;
        #pragma unroll
        for (int t = 0; t < 7; t++) {
            ex0 += eav[t] * wc[t * 192 + 0];
            ex1 += eav[t] * wc[t * 192 + 1];
            ex2 += eav[t] * wc[t * 192 + 2];
            ex3 += eav[t] * wc[t * 192 + 3];
        }
        float4 m = make_float4(al1 * (v.x + ex0), al1 * (v.y + ex1),
                               al1 * (v.z + ex2), al1 * (v.w + ex3));
        atomicAdd(&ar[c], m);
    }
    if (lane < 16) {
        int c = lane + 32;
        float4 v = vr[c];
        const float* wc = &sW[4 * c];
        float ex0=0.f, ex1=0.f, ex2=0.f, ex3=0.f;
        #pragma unroll
        for (int t = 0; t < 7; t++) {
            ex0 += eav[t] * wc[t * 192 + 0];
            ex1 += eav[t] * wc[t * 192 + 1];
            ex2 += eav[t] * wc[t * 192 + 2];
            ex3 += eav[t] * wc[t * 192 + 3];
        }
        float4 m = make_float4(al2 * (v.x + ex0), al2 * (v.y + ex1),
                               al2 * (v.z + ex2), al2 * (v.w + ex3));
        atomicAdd(&ar[c], m);
    }
}

// ---------------- conv2 node GEMM: elu(acc1) [N,192] @ [192,256] -------------
__global__ void k_gemm2(const float* __restrict__ qw, const float* __restrict__ qb,
                        const float* __restrict__ kw, const float* __restrict__ kb,
                        const float* __restrict__ vw, const float* __restrict__ vb,
                        const float* __restrict__ sw, const float* __restrict__ sb,
                        int n) {
    __shared__ float4 sh[32 * 48];          // elu'd h3 tile [32,192]
    int tid = threadIdx.x;                  // 256 threads
    int arr = tid >> 6, cc = tid & 63;
    const float* W = arr == 0 ? qw : arr == 1 ? kw : arr == 2 ? vw : sw;
    float bias = (arr == 0 ? qb : arr == 1 ? kb : arr == 2 ? vb : sb)[cc];
    float* outp = (float*)(arr == 0 ? g_q2 : arr == 1 ? g_k2 : arr == 2 ? g_v2 : g_acc2);
    int base = blockIdx.x * 32;
    int cnt  = min(32, n - base);
    for (int i = tid; i < cnt * 48; i += 256) {
        float4 v = g_acc1[base * 48 + i];
        v.x = eluf(v.x); v.y = eluf(v.y); v.z = eluf(v.z); v.w = eluf(v.w);
        sh[i] = v;
    }
    __syncthreads();
    float acc[32];
    #pragma unroll
    for (int i = 0; i < 32; i++) acc[i] = bias;
    #pragma unroll 4
    for (int k4 = 0; k4 < 48; k4++) {
        float w0 = W[(4 * k4 + 0) * 64 + cc];
        float w1 = W[(4 * k4 + 1) * 64 + cc];
        float w2 = W[(4 * k4 + 2) * 64 + cc];
        float w3 = W[(4 * k4 + 3) * 64 + cc];
        #pragma unroll
        for (int nn = 0; nn < 32; nn++) {
            float4 h = sh[nn * 48 + k4];
            acc[nn] += h.x * w0 + h.y * w1 + h.z * w2 + h.w * w3;
        }
    }
    for (int nn = 0; nn < cnt; nn++) outp[(base + nn) * 64 + cc] = acc[nn];
}

// ---------------- conv2 edge pass 1 ------------------------------------------
__global__ void k_edge3(const int* __restrict__ src, const int* __restrict__ dst,
                        const float* __restrict__ ea, const float* __restrict__ ew, int E) {
    __shared__ float sW[448];               // e2_w [7,64]
    int tid = threadIdx.x;
    for (int i = tid; i < 448; i += 256) sW[i] = ew[i];
    __syncthreads();
    int e = (blockIdx.x * 256 + tid) >> 5;
    int lane = tid & 31;
    if (e >= E) return;
    int s = src[e], d = dst[e];
    float eav[7];
    #pragma unroll
    for (int t = 0; t < 7; t++) eav[t] = ea[e * 7 + t];
    float2 q = *(const float2*)((const float*)g_q2 + d * 64 + lane * 2);
    float2 k = *(const float2*)((const float*)g_k2 + s * 64 + lane * 2);
    float e0 = 0.f, e1 = 0.f;
    #pragma unroll
    for (int t = 0; t < 7; t++) {
        e0 += eav[t] * sW[t * 64 + 2 * lane];
        e1 += eav[t] * sW[t * 64 + 2 * lane + 1];
    }
    float part = q.x * (k.x + e0) + q.y * (k.y + e1);
    part += __shfl_xor_sync(0xffffffffu, part, 1);
    part += __shfl_xor_sync(0xffffffffu, part, 2);
    if ((lane & 3) == 0) {
        int h = lane >> 2;
        float ex = __expf(part * 0.35355339059327373f);   // 1/sqrt(8)
        g_ex2[e * 8 + h] = ex;
        atomicAdd(&g_den2[d * 8 + h], ex);
    }
}

// ---------------- conv2 edge pass 2 ------------------------------------------
__global__ void k_edge4(const int* __restrict__ src, const int* __restrict__ dst,
                        const float* __restrict__ ea, const float* __restrict__ ew, int E) {
    __shared__ float sW[448];
    int tid = threadIdx.x;
    for (int i = tid; i < 448; i += 256) sW[i] = ew[i];
    __syncthreads();
    int e = (blockIdx.x * 256 + tid) >> 5;
    int lane = tid & 31;
    if (e >= E) return;
    int s = src[e], d = dst[e];
    float eav[7];
    #pragma unroll
    for (int t = 0; t < 7; t++) eav[t] = ea[e * 7 + t];
    float a = 0.f;
    if (lane < 8) a = g_ex2[e * 8 + lane] / g_den2[d * 8 + lane];
    float al = __shfl_sync(0xffffffffu, a, lane >> 2);
    float2 v = *(const float2*)((const float*)g_v2 + s * 64 + lane * 2);
    float e0 = 0.f, e1 = 0.f;
    #pragma unroll
    for (int t = 0; t < 7; t++) {
        e0 += eav[t] * sW[t * 64 + 2 * lane];
        e1 += eav[t] * sW[t * 64 + 2 * lane + 1];
    }
    float2 m = make_float2(al * (v.x + e0), al * (v.y + e1));
    atomicAdd((float2*)((float*)g_acc2 + d * 64 + lane * 2), m);
}

// ---------------- head: elu -> lin1(64,20) -> elu -> lin2(20,1) --------------
__global__ void k_final(const float* __restrict__ w1, const float* __restrict__ b1,
                        const float* __restrict__ w2, const float* __restrict__ b2,
                        float* __restrict__ out, int n) {
    __shared__ float sw1[64 * 20], sb1[20], sw2[20], sb2v[1];
    int tid = threadIdx.x;
    for (int i = tid; i < 1280; i += 256) sw1[i] = w1[i];
    if (tid < 20) { sb1[tid] = b1[tid]; sw2[tid] = w2[tid]; }
    if (tid == 0) sb2v[0] = b2[0];
    __syncthreads();
    int node = blockIdx.x * 256 + tid;
    if (node >= n) return;
    float h[64];
    const float4* r = g_acc2 + node * 16;
    #pragma unroll
    for (int i = 0; i < 16; i++) {
        float4 v = r[i];
        h[4 * i]     = eluf(v.x);
        h[4 * i + 1] = eluf(v.y);
        h[4 * i + 2] = eluf(v.z);
        h[4 * i + 3] = eluf(v.w);
    }
    float res = sb2v[0];
    #pragma unroll 4
    for (int j = 0; j < 20; j++) {
        float a = sb1[j];
        #pragma unroll
        for (int k = 0; k < 64; k++) a += h[k] * sw1[k * 20 + j];
        res += eluf(a) * sw2[j];
    }
    out[node] = res;
}

// ---------------- host launcher ----------------------------------------------
extern "C" void kernel_launch(void* const* d_in, const int* in_sizes, int n_in,
                              void* d_out, int out_size) {
    const float* x      = (const float*)d_in[0];
    const int*   ei     = (const int*)  d_in[1];
    const float* ea     = (const float*)d_in[2];
    const float* linA_w = (const float*)d_in[3];
    const float* linA_b = (const float*)d_in[4];
    const float* linB_w = (const float*)d_in[5];
    const float* linB_b = (const float*)d_in[6];
    const float* q1_w   = (const float*)d_in[7];
    const float* q1_b   = (const float*)d_in[8];
    const float* k1_w   = (const float*)d_in[9];
    const float* k1_b   = (const float*)d_in[10];
    const float* v1_w   = (const float*)d_in[11];
    const float* v1_b   = (const float*)d_in[12];
    const float* e1_w   = (const float*)d_in[13];
    const float* s1_w   = (const float*)d_in[14];
    const float* s1_b   = (const float*)d_in[15];
    const float* q2_w   = (const float*)d_in[16];
    const float* q2_b   = (const float*)d_in[17];
    const float* k2_w   = (const float*)d_in[18];
    const float* k2_b   = (const float*)d_in[19];
    const float* v2_w   = (const float*)d_in[20];
    const float* v2_b   = (const float*)d_in[21];
    const float* e2_w   = (const float*)d_in[22];
    const float* s2_w   = (const float*)d_in[23];
    const float* s2_b   = (const float*)d_in[24];
    const float* lin1_w = (const float*)d_in[25];
    const float* lin1_b = (const float*)d_in[26];
    const float* lin2_w = (const float*)d_in[27];
    const float* lin2_b = (const float*)d_in[28];

    int n = in_sizes[0] / 23;
    int E = in_sizes[1] / 2;
    const int* src = ei;
    const int* dst = ei + E;
    float* out = (float*)d_out;

    int eblocks = (E + 7) / 8;   // 8 edges (warps) per 256-thread block

    k_zero <<<(n * 8 + 255) / 256, 256>>>(n * 8);
    k_h2   <<<(n + 255) / 256, 256>>>(x, linA_w, linA_b, linB_w, linB_b, n);
    k_gemm1<<<(n + 127) / 128, 768>>>(q1_w, q1_b, k1_w, k1_b, v1_w, v1_b, s1_w, s1_b, n);
    k_edge1<<<eblocks, 256>>>(src, dst, ea, e1_w, E);
    k_edge2<<<eblocks, 256>>>(src, dst, ea, e1_w, E);
    k_gemm2<<<(n + 31) / 32, 256>>>(q2_w, q2_b, k2_w, k2_b, v2_w, v2_b, s2_w, s2_b, n);
    k_edge3<<<eblocks, 256>>>(src, dst, ea, e2_w, E);
    k_edge4<<<eblocks, 256>>>(src, dst, ea, e2_w, E);
    k_final<<<(n + 255) / 256, 256>>>(lin1_w, lin1_b, lin2_w, lin2_b, out, n);
}

// round 2
// speedup vs baseline: 1.1837x; 1.1837x over previous
#include <cuda_runtime.h>
#include <cuda_bf16.h>

#define NMAX 100000
#define EMAX 800000

// ---------------- scratch (device globals; no runtime allocation) ------------
__device__ float4 g_h2  [NMAX * 6];    // [N,24] padded (23 + 1 zero)
__device__ float4 g_q1  [NMAX * 48];   // [N,192]
__device__ float4 g_kv1 [NMAX * 96];   // [N,384]: k | v interleaved per node
__device__ float4 g_acc1[NMAX * 48];   // skip, then conv1 out (pre-elu)
__device__ float4 g_q2  [NMAX * 16];   // [N,64]
__device__ float4 g_kv2 [NMAX * 32];   // [N,128]: k | v
__device__ float4 g_acc2[NMAX * 16];   // conv2 out (pre-elu)
// CSR scratch
__device__ int  g_deg   [NMAX];
__device__ int  g_part  [NMAX];
__device__ int  g_bsum  [512];
__device__ int  g_rowptr[NMAX];
__device__ int  g_cursor[NMAX];
__device__ int2 g_cpack [EMAX];        // (src, edge_id) sorted by dst

__device__ __forceinline__ float eluf(float x) { return x > 0.f ? x : expm1f(x); }

// ---------------- CSR build ---------------------------------------------------
__global__ void k_zero(int n) {
    int i = blockIdx.x * blockDim.x + threadIdx.x;
    if (i < n) g_deg[i] = 0;
}
__global__ void k_count(const int* __restrict__ dst, int E) {
    int e = blockIdx.x * blockDim.x + threadIdx.x;
    if (e < E) atomicAdd(&g_deg[dst[e]], 1);
}
__global__ void k_scanA(int n) {                 // 256 threads/block
    __shared__ int s[256];
    int tid = threadIdx.x, i = blockIdx.x * 256 + tid;
    int v = (i < n) ? g_deg[i] : 0;
    s[tid] = v; __syncthreads();
    #pragma unroll
    for (int off = 1; off < 256; off <<= 1) {
        int t = (tid >= off) ? s[tid - off] : 0;
        __syncthreads();
        s[tid] += t;
        __syncthreads();
    }
    if (i < n) g_part[i] = s[tid] - v;           // exclusive within block
    if (tid == 255) g_bsum[blockIdx.x] = s[255];
}
__global__ void k_scanB(int nb) {                // single block, 512 threads
    __shared__ int s[512];
    int tid = threadIdx.x;
    int v = (tid < nb) ? g_bsum[tid] : 0;
    s[tid] = v; __syncthreads();
    #pragma unroll
    for (int off = 1; off < 512; off <<= 1) {
        int t = (tid >= off) ? s[tid - off] : 0;
        __syncthreads();
        s[tid] += t;
        __syncthreads();
    }
    g_bsum[tid] = s[tid] - v;                    // exclusive block offsets
}
__global__ void k_scanC(int n) {
    int i = blockIdx.x * blockDim.x + threadIdx.x;
    if (i < n) {
        int r = g_part[i] + g_bsum[i >> 8];
        g_rowptr[i] = r;
        g_cursor[i] = r;
    }
}
__global__ void k_scatter(const int* __restrict__ src, const int* __restrict__ dst, int E) {
    int e = blockIdx.x * blockDim.x + threadIdx.x;
    if (e < E) {
        int d = dst[e];
        int pos = atomicAdd(&g_cursor[d], 1);
        g_cpack[pos] = make_int2(src[e], e);
    }
}

// ---------------- h2 = elu(elu(x@A+bA)@B+bB), padded to 24 -------------------
__global__ void k_h2(const float* __restrict__ x,
                     const float* __restrict__ Aw, const float* __restrict__ Ab,
                     const float* __restrict__ Bw, const float* __restrict__ Bb,
                     int n) {
    __shared__ float sA[23 * 23], sB[23 * 23], sbA[23], sbB[23];
    __shared__ float sx[256 * 23];
    int tid = threadIdx.x;
    for (int i = tid; i < 23 * 23; i += 256) { sA[i] = Aw[i]; sB[i] = Bw[i]; }
    if (tid < 23) { sbA[tid] = Ab[tid]; sbB[tid] = Bb[tid]; }
    int base = blockIdx.x * 256;
    int cnt  = min(256, n - base);
    for (int i = tid; i < cnt * 23; i += 256) sx[i] = x[base * 23 + i];
    __syncthreads();
    if (tid < cnt) {
        const float* xr = &sx[tid * 23];
        float h1[23];
        #pragma unroll
        for (int j = 0; j < 23; j++) {
            float a = sbA[j];
            #pragma unroll
            for (int k = 0; k < 23; k++) a += xr[k] * sA[k * 23 + j];
            h1[j] = eluf(a);
        }
        float* out = (float*)g_h2 + (base + tid) * 24;
        #pragma unroll
        for (int j = 0; j < 23; j++) {
            float a = sbB[j];
            #pragma unroll
            for (int k = 0; k < 23; k++) a += h1[k] * sB[k * 23 + j];
            out[j] = eluf(a);
        }
        out[23] = 0.f;
    }
}

// ---------------- conv1 node GEMM: [N,24]@[24,768] ----------------------------
__global__ void k_gemm1(const float* __restrict__ qw, const float* __restrict__ qb,
                        const float* __restrict__ kw, const float* __restrict__ kb,
                        const float* __restrict__ vw, const float* __restrict__ vb,
                        const float* __restrict__ sw, const float* __restrict__ sb,
                        int n) {
    __shared__ float4 sh[128 * 6];
    int tid = threadIdx.x;                  // 768 threads
    int arr = tid / 192, cc = tid % 192;
    const float* W = arr == 0 ? qw : arr == 1 ? kw : arr == 2 ? vw : sw;
    const float* B = arr == 0 ? qb : arr == 1 ? kb : arr == 2 ? vb : sb;
    float w[24];
    #pragma unroll
    for (int k = 0; k < 23; k++) w[k] = W[k * 192 + cc];
    w[23] = 0.f;
    float bias = B[cc];
    int base = blockIdx.x * 128;
    int cnt  = min(128, n - base);
    for (int i = tid; i < cnt * 6; i += 768) sh[i] = g_h2[base * 6 + i];
    __syncthreads();
    for (int nn = 0; nn < cnt; nn++) {
        float a = bias;
        #pragma unroll
        for (int k4 = 0; k4 < 6; k4++) {
            float4 h = sh[nn * 6 + k4];
            a += h.x * w[4 * k4] + h.y * w[4 * k4 + 1] + h.z * w[4 * k4 + 2] + h.w * w[4 * k4 + 3];
        }
        int node = base + nn;
        if (arr == 0)      ((float*)g_q1)[node * 192 + cc] = a;
        else if (arr == 1) ((float*)g_kv1)[node * 384 + cc] = a;
        else if (arr == 2) ((float*)g_kv1)[node * 384 + 192 + cc] = a;
        else               ((float*)g_acc1)[node * 192 + cc] = a;
    }
}

// ---------------- conv1: node-centric fused softmax-aggregate -----------------
// warp per dst node; single pass (no max-subtraction, softmax is linear).
__global__ void k_conv1(const float* __restrict__ ea, const float* __restrict__ ew, int n) {
    __shared__ float sW[1344];              // e1_w [7,192]
    int tid = threadIdx.x;
    for (int i = tid; i < 1344; i += 256) sW[i] = ew[i];
    __syncthreads();
    int node = blockIdx.x * 8 + (tid >> 5);
    int lane = tid & 31;
    if (node >= n) return;
    int deg = g_deg[node];
    if (deg == 0) return;                   // acc1 already holds skip
    int rs = g_rowptr[node];

    // q row: channels [lane*6, lane*6+6)
    const float* qr = (const float*)g_q1 + node * 192 + lane * 6;
    float q0, q1, q2, q3, q4, q5;
    { float2 a = *(const float2*)qr;       q0 = a.x; q1 = a.y;
      float2 b = *(const float2*)(qr + 2); q2 = b.x; q3 = b.y;
      float2 c = *(const float2*)(qr + 4); q4 = c.x; q5 = c.y; }

    // pq[t] = sum_c q_c * We[t,c] over this head's 24 channels (group of 4 lanes)
    float pqh[7];
    #pragma unroll
    for (int t = 0; t < 7; t++) {
        const float* w = &sW[t * 192 + lane * 6];
        float p = q0 * w[0] + q1 * w[1] + q2 * w[2] + q3 * w[3] + q4 * w[4] + q5 * w[5];
        p += __shfl_xor_sync(0xffffffffu, p, 1);
        p += __shfl_xor_sync(0xffffffffu, p, 2);
        pqh[t] = p;
    }

    float acc0 = 0.f, acc1 = 0.f, acc2 = 0.f, acc3 = 0.f, acc4 = 0.f, acc5 = 0.f;
    float den = 0.f, a0 = 0.f, a1 = 0.f;
    int g = lane & 3;                       // sub-lane in head group

    int2 se = g_cpack[rs];
    for (int i = 0; i < deg; i++) {
        int2 cur = se;
        if (i + 1 < deg) se = g_cpack[rs + i + 1];
        int s = cur.x, eid = cur.y;
        float eav[7];
        #pragma unroll
        for (int t = 0; t < 7; t++) eav[t] = __ldg(&ea[eid * 7 + t]);
        const float* kv = (const float*)g_kv1 + s * 384 + lane * 6;
        float k0, k1, k2, k3, k4, k5, v0, v1, v2, v3, v4, v5;
        { float2 a = *(const float2*)kv;         k0 = a.x; k1 = a.y;
          float2 b = *(const float2*)(kv + 2);   k2 = b.x; k3 = b.y;
          float2 c = *(const float2*)(kv + 4);   k4 = c.x; k5 = c.y;
          float2 p = *(const float2*)(kv + 192); v0 = p.x; v1 = p.y;
          float2 r = *(const float2*)(kv + 194); v2 = r.x; v3 = r.y;
          float2 u = *(const float2*)(kv + 196); v4 = u.x; v5 = u.y; }
        float lp = q0 * k0 + q1 * k1 + q2 * k2 + q3 * k3 + q4 * k4 + q5 * k5;
        lp += __shfl_xor_sync(0xffffffffu, lp, 1);
        lp += __shfl_xor_sync(0xffffffffu, lp, 2);
        #pragma unroll
        for (int t = 0; t < 7; t++) lp += eav[t] * pqh[t];
        float ex = __expf(lp * 0.20412414523193154f);   // 1/sqrt(24)
        den += ex;
        acc0 += ex * v0; acc1 += ex * v1; acc2 += ex * v2;
        acc3 += ex * v3; acc4 += ex * v4; acc5 += ex * v5;
        // a0/a1 accumulate ex*ea for this lane's t-slots: lane g -> t = 2g, 2g+1
        float elo = g == 0 ? eav[0] : g == 1 ? eav[2] : g == 2 ? eav[4] : eav[6];
        float ehi = g == 0 ? eav[1] : g == 1 ? eav[3] : g == 2 ? eav[5] : 0.f;
        a0 += ex * elo;
        a1 += ex * ehi;
    }

    float inv = 1.f / den;
    int base = lane & ~3;
    float ae[7];
    ae[0] = __shfl_sync(0xffffffffu, a0, base);
    ae[1] = __shfl_sync(0xffffffffu, a1, base);
    ae[2] = __shfl_sync(0xffffffffu, a0, base + 1);
    ae[3] = __shfl_sync(0xffffffffu, a1, base + 1);
    ae[4] = __shfl_sync(0xffffffffu, a0, base + 2);
    ae[5] = __shfl_sync(0xffffffffu, a1, base + 2);
    ae[6] = __shfl_sync(0xffffffffu, a0, base + 3);

    float m[6] = {acc0, acc1, acc2, acc3, acc4, acc5};
    const float* wb = &sW[lane * 6];
    #pragma unroll
    for (int j = 0; j < 6; j++) {
        #pragma unroll
        for (int t = 0; t < 7; t++) m[j] += ae[t] * wb[t * 192 + j];
    }
    float* outp = (float*)g_acc1 + node * 192 + lane * 6;
    #pragma unroll
    for (int j2 = 0; j2 < 3; j2++) {
        float2 sk = *(float2*)(outp + 2 * j2);
        sk.x += m[2 * j2] * inv;
        sk.y += m[2 * j2 + 1] * inv;
        *(float2*)(outp + 2 * j2) = sk;
    }
}

// ---------------- conv2 node GEMM: elu(acc1) [N,192] @ [192,256] --------------
__global__ void k_gemm2(const float* __restrict__ qw, const float* __restrict__ qb,
                        const float* __restrict__ kw, const float* __restrict__ kb,
                        const float* __restrict__ vw, const float* __restrict__ vb,
                        const float* __restrict__ sw, const float* __restrict__ sb,
                        int n) {
    __shared__ float4 sh[32 * 48];          // elu'd h3 tile [32,192]
    int tid = threadIdx.x;                  // 256 threads
    int arr = tid >> 6, cc = tid & 63;
    const float* W = arr == 0 ? qw : arr == 1 ? kw : arr == 2 ? vw : sw;
    float bias = (arr == 0 ? qb : arr == 1 ? kb : arr == 2 ? vb : sb)[cc];
    int base = blockIdx.x * 32;
    int cnt  = min(32, n - base);
    for (int i = tid; i < cnt * 48; i += 256) {
        float4 v = g_acc1[base * 48 + i];
        v.x = eluf(v.x); v.y = eluf(v.y); v.z = eluf(v.z); v.w = eluf(v.w);
        sh[i] = v;
    }
    __syncthreads();
    float acc[32];
    #pragma unroll
    for (int i = 0; i < 32; i++) acc[i] = bias;
    #pragma unroll 4
    for (int k4 = 0; k4 < 48; k4++) {
        float w0 = W[(4 * k4 + 0) * 64 + cc];
        float w1 = W[(4 * k4 + 1) * 64 + cc];
        float w2 = W[(4 * k4 + 2) * 64 + cc];
        float w3 = W[(4 * k4 + 3) * 64 + cc];
        #pragma unroll
        for (int nn = 0; nn < 32; nn++) {
            float4 h = sh[nn * 48 + k4];
            acc[nn] += h.x * w0 + h.y * w1 + h.z * w2 + h.w * w3;
        }
    }
    for (int nn = 0; nn < cnt; nn++) {
        int node = base + nn;
        if (arr == 0)      ((float*)g_q2)[node * 64 + cc] = acc[nn];
        else if (arr == 1) ((float*)g_kv2)[node * 128 + cc] = acc[nn];
        else if (arr == 2) ((float*)g_kv2)[node * 128 + 64 + cc] = acc[nn];
        else               ((float*)g_acc2)[node * 64 + cc] = acc[nn];
    }
}

// ---------------- conv2: node-centric fused softmax-aggregate -----------------
__global__ void k_conv2(const float* __restrict__ ea, const float* __restrict__ ew, int n) {
    __shared__ float sW[448];               // e2_w [7,64]
    int tid = threadIdx.x;
    for (int i = tid; i < 448; i += 256) sW[i] = ew[i];
    __syncthreads();
    int node = blockIdx.x * 8 + (tid >> 5);
    int lane = tid & 31;
    if (node >= n) return;
    int deg = g_deg[node];
    if (deg == 0) return;
    int rs = g_rowptr[node];

    const float* qr = (const float*)g_q2 + node * 64 + lane * 2;
    float2 qv = *(const float2*)qr;

    float pqh[7];
    #pragma unroll
    for (int t = 0; t < 7; t++) {
        const float* w = &sW[t * 64 + lane * 2];
        float p = qv.x * w[0] + qv.y * w[1];
        p += __shfl_xor_sync(0xffffffffu, p, 1);
        p += __shfl_xor_sync(0xffffffffu, p, 2);
        pqh[t] = p;
    }

    float acc0 = 0.f, acc1 = 0.f, den = 0.f, a0 = 0.f, a1 = 0.f;
    int g = lane & 3;

    int2 se = g_cpack[rs];
    for (int i = 0; i < deg; i++) {
        int2 cur = se;
        if (i + 1 < deg) se = g_cpack[rs + i + 1];
        int s = cur.x, eid = cur.y;
        float eav[7];
        #pragma unroll
        for (int t = 0; t < 7; t++) eav[t] = __ldg(&ea[eid * 7 + t]);
        const float* kv = (const float*)g_kv2 + s * 128 + lane * 2;
        float2 kk = *(const float2*)kv;
        float2 vv = *(const float2*)(kv + 64);
        float lp = qv.x * kk.x + qv.y * kk.y;
        lp += __shfl_xor_sync(0xffffffffu, lp, 1);
        lp += __shfl_xor_sync(0xffffffffu, lp, 2);
        #pragma unroll
        for (int t = 0; t < 7; t++) lp += eav[t] * pqh[t];
        float ex = __expf(lp * 0.35355339059327373f);   // 1/sqrt(8)
        den += ex;
        acc0 += ex * vv.x;
        acc1 += ex * vv.y;
        float elo = g == 0 ? eav[0] : g == 1 ? eav[2] : g == 2 ? eav[4] : eav[6];
        float ehi = g == 0 ? eav[1] : g == 1 ? eav[3] : g == 2 ? eav[5] : 0.f;
        a0 += ex * elo;
        a1 += ex * ehi;
    }

    float inv = 1.f / den;
    int base = lane & ~3;
    float ae[7];
    ae[0] = __shfl_sync(0xffffffffu, a0, base);
    ae[1] = __shfl_sync(0xffffffffu, a1, base);
    ae[2] = __shfl_sync(0xffffffffu, a0, base + 1);
    ae[3] = __shfl_sync(0xffffffffu, a1, base + 1);
    ae[4] = __shfl_sync(0xffffffffu, a0, base + 2);
    ae[5] = __shfl_sync(0xffffffffu, a1, base + 2);
    ae[6] = __shfl_sync(0xffffffffu, a0, base + 3);

    float m0 = acc0, m1 = acc1;
    const float* wb = &sW[lane * 2];
    #pragma unroll
    for (int t = 0; t < 7; t++) {
        m0 += ae[t] * wb[t * 64];
        m1 += ae[t] * wb[t * 64 + 1];
    }
    float* outp = (float*)g_acc2 + node * 64 + lane * 2;
    float2 sk = *(float2*)outp;
    sk.x += m0 * inv;
    sk.y += m1 * inv;
    *(float2*)outp = sk;
}

// ---------------- head: elu -> lin1(64,20) -> elu -> lin2(20,1) --------------
__global__ void k_final(const float* __restrict__ w1, const float* __restrict__ b1,
                        const float* __restrict__ w2, const float* __restrict__ b2,
                        float* __restrict__ out, int n) {
    __shared__ float sw1[64 * 20], sb1[20], sw2[20], sb2v[1];
    int tid = threadIdx.x;
    for (int i = tid; i < 1280; i += 256) sw1[i] = w1[i];
    if (tid < 20) { sb1[tid] = b1[tid]; sw2[tid] = w2[tid]; }
    if (tid == 0) sb2v[0] = b2[0];
    __syncthreads();
    int node = blockIdx.x * 256 + tid;
    if (node >= n) return;
    float h[64];
    const float4* r = g_acc2 + node * 16;
    #pragma unroll
    for (int i = 0; i < 16; i++) {
        float4 v = r[i];
        h[4 * i]     = eluf(v.x);
        h[4 * i + 1] = eluf(v.y);
        h[4 * i + 2] = eluf(v.z);
        h[4 * i + 3] = eluf(v.w);
    }
    float res = sb2v[0];
    #pragma unroll 4
    for (int j = 0; j < 20; j++) {
        float a = sb1[j];
        #pragma unroll
        for (int k = 0; k < 64; k++) a += h[k] * sw1[k * 20 + j];
        res += eluf(a) * sw2[j];
    }
    out[node] = res;
}

// ---------------- host launcher ----------------------------------------------
extern "C" void kernel_launch(void* const* d_in, const int* in_sizes, int n_in,
                              void* d_out, int out_size) {
    const float* x      = (const float*)d_in[0];
    const int*   ei     = (const int*)  d_in[1];
    const float* ea     = (const float*)d_in[2];
    const float* linA_w = (const float*)d_in[3];
    const float* linA_b = (const float*)d_in[4];
    const float* linB_w = (const float*)d_in[5];
    const float* linB_b = (const float*)d_in[6];
    const float* q1_w   = (const float*)d_in[7];
    const float* q1_b   = (const float*)d_in[8];
    const float* k1_w   = (const float*)d_in[9];
    const float* k1_b   = (const float*)d_in[10];
    const float* v1_w   = (const float*)d_in[11];
    const float* v1_b   = (const float*)d_in[12];
    const float* e1_w   = (const float*)d_in[13];
    const float* s1_w   = (const float*)d_in[14];
    const float* s1_b   = (const float*)d_in[15];
    const float* q2_w   = (const float*)d_in[16];
    const float* q2_b   = (const float*)d_in[17];
    const float* k2_w   = (const float*)d_in[18];
    const float* k2_b   = (const float*)d_in[19];
    const float* v2_w   = (const float*)d_in[20];
    const float* v2_b   = (const float*)d_in[21];
    const float* e2_w   = (const float*)d_in[22];
    const float* s2_w   = (const float*)d_in[23];
    const float* s2_b   = (const float*)d_in[24];
    const float* lin1_w = (const float*)d_in[25];
    const float* lin1_b = (const float*)d_in[26];
    const float* lin2_w = (const float*)d_in[27];
    const float* lin2_b = (const float*)d_in[28];

    int n = in_sizes[0] / 23;
    int E = in_sizes[1] / 2;
    const int* src = ei;
    const int* dst = ei + E;
    float* out = (float*)d_out;

    int nb256  = (n + 255) / 256;
    int eb256  = (E + 255) / 256;
    int nbconv = (n + 7) / 8;

    // CSR build
    k_zero   <<<nb256, 256>>>(n);
    k_count  <<<eb256, 256>>>(dst, E);
    k_scanA  <<<nb256, 256>>>(n);
    k_scanB  <<<1, 512>>>(nb256);
    k_scanC  <<<nb256, 256>>>(n);
    k_scatter<<<eb256, 256>>>(src, dst, E);

    // network
    k_h2   <<<nb256, 256>>>(x, linA_w, linA_b, linB_w, linB_b, n);
    k_gemm1<<<(n + 127) / 128, 768>>>(q1_w, q1_b, k1_w, k1_b, v1_w, v1_b, s1_w, s1_b, n);
    k_conv1<<<nbconv, 256>>>(ea, e1_w, n);
    k_gemm2<<<(n + 31) / 32, 256>>>(q2_w, q2_b, k2_w, k2_b, v2_w, v2_b, s2_w, s2_b, n);
    k_conv2<<<nbconv, 256>>>(ea, e2_w, n);
    k_final<<<nb256, 256>>>(lin1_w, lin1_b, lin2_w, lin2_b, out, n);
}